// round 15
// baseline (speedup 1.0000x reference)
#include <cuda_runtime.h>
#include <cuda_fp16.h>
#include <cstdint>

// ---------------- problem constants ----------------
#define NS    48
#define DIM   256
#define H     8
#define HD    32
#define NW    1728
#define NTOK  110592
#define QKVN  768

// A-resident fp16 GEMM geometry (m-tile 128, 2-stage B ring -> 3 CTAs/SM)
#define A_BYTES   65536
#define B_STAGE   4096
#define B_STAGES  2
#define GEMM_SMEM (A_BYTES + B_STAGES * B_STAGE)   // 73728 -> 3 CTAs/SM incl. 1KB reserve

// ---------------- scratch ----------------
__device__ __align__(16) __half g_qkvh[(size_t)NTOK * QKVN];  // qkv output, fp16
__device__ __align__(16) __half g_xh[(size_t)NTOK * DIM];     // x as fp16
__device__ __align__(16) __half g_ah[(size_t)NTOK * DIM];     // attn out, fp16
__device__ __align__(16) __half g_wqkv_h[(size_t)QKVN * DIM];
__device__ __align__(16) __half g_wout_h[(size_t)DIM * DIM];

__device__ __forceinline__ int src_token(int t) {
    int win = t >> 6, i = t & 63;
    int a = win / 144, b = (win / 12) % 12, c = win % 12;
    int ix = i >> 4, iy = (i >> 2) & 3, iz = i & 3;
    int X = a * 4 + ix + 2; if (X >= NS) X -= NS;
    int Y = b * 4 + iy + 2; if (Y >= NS) Y -= NS;
    int Z = c * 4 + iz + 2; if (Z >= NS) Z -= NS;
    return (X * NS + Y) * NS + Z;
}

// ---------------- MMA / ldmatrix / cp.async helpers ----------------
__device__ __forceinline__ void mma_fp16(float* d, const unsigned* a, const unsigned* b) {
    asm volatile(
        "mma.sync.aligned.m16n8k16.row.col.f32.f16.f16.f32 "
        "{%0,%1,%2,%3},{%4,%5,%6,%7},{%8,%9},{%0,%1,%2,%3};"
        : "+f"(d[0]), "+f"(d[1]), "+f"(d[2]), "+f"(d[3])
        : "r"(a[0]), "r"(a[1]), "r"(a[2]), "r"(a[3]), "r"(b[0]), "r"(b[1]));
}
__device__ __forceinline__ void ldsm_x4(uint32_t addr, unsigned r[4]) {
    asm volatile("ldmatrix.sync.aligned.m8n8.x4.shared.b16 {%0,%1,%2,%3}, [%4];"
                 : "=r"(r[0]), "=r"(r[1]), "=r"(r[2]), "=r"(r[3]) : "r"(addr));
}
#define CP_ASYNC16(dst, src) \
    asm volatile("cp.async.ca.shared.global [%0], [%1], 16;" :: "r"(dst), "l"(src) : "memory")
#define CP_COMMIT() asm volatile("cp.async.commit_group;" ::: "memory")
#define CP_WAIT0()  asm volatile("cp.async.wait_group 0;" ::: "memory")

// ---------------- prep kernels ----------------
__global__ __launch_bounds__(256) void convert_x_kernel(const float4* __restrict__ x) {
    size_t i = (size_t)blockIdx.x * blockDim.x + threadIdx.x;
    float4 v = x[i];
    ((__half2*)g_xh)[2 * i]     = __floats2half2_rn(v.x, v.y);
    ((__half2*)g_xh)[2 * i + 1] = __floats2half2_rn(v.z, v.w);
}

template<bool QKV>
__global__ void transpose_cvt(const float* __restrict__ W) {
    __shared__ float tile[32][33];
    const int N = QKV ? QKVN : DIM;
    __half* Wh = QKV ? g_wqkv_h : g_wout_h;
    int bx = blockIdx.x * 32, by = blockIdx.y * 32;
    #pragma unroll
    for (int i = 0; i < 32; i += 8)
        tile[threadIdx.y + i][threadIdx.x] = W[(size_t)(by + threadIdx.y + i) * N + bx + threadIdx.x];
    __syncthreads();
    #pragma unroll
    for (int i = 0; i < 32; i += 8)
        Wh[(size_t)(bx + threadIdx.y + i) * DIM + by + threadIdx.x] =
            __float2half_rn(tile[threadIdx.x][threadIdx.y + i]);
}

// ---------------- A-resident fp16 GEMM, 2-stage B ring, 3 CTAs/SM -------------
template<int NBLK, bool GATHER_A, bool SCATTER_OUT, bool OUT_HALF>
__global__ __launch_bounds__(256, 3) void gemm_fp16k(
        const float* __restrict__ bias, float* __restrict__ OutExt) {
    extern __shared__ char smc[];
    const uint32_t ABASE = (uint32_t)__cvta_generic_to_shared(smc);
    const uint32_t BBASE = ABASE + A_BYTES;

    const int tid = threadIdx.x;
    const int warp = tid >> 5, lane = tid & 31;
    const int g = lane >> 2, l4 = lane & 3;
    const int wm = (warp >> 2) * 64, wn = (warp & 3) * 32;

    const __half* Ah = GATHER_A ? g_xh : g_ah;
    const __half* Bh = GATHER_A ? g_wqkv_h : g_wout_h;
    const int NOUT = NBLK * 128;

    const int mb = blockIdx.x * 128;
    const int lrow = tid & 127;
    const int half = tid >> 7;

    // ---- load A plane once ----
    {
        const int tok = GATHER_A ? src_token(mb + lrow) : (mb + lrow);
        const __half* a0 = Ah + (size_t)tok * DIM + half * 8;
        const uint32_t d0 = ABASE + half * 2048 + lrow * 16;
        #pragma unroll
        for (int kt = 0; kt < 16; kt++)
            CP_ASYNC16(d0 + kt * 4096, a0 + kt * 16);
        CP_COMMIT();
    }

    const __half* bRow = Bh + (size_t)lrow * DIM + half * 8;
    const uint32_t bDst = BBASE + half * 2048 + lrow * 16;

    // prologue: chunk 0
    CP_ASYNC16(bDst, bRow);
    CP_COMMIT();

    const int rowsel = (lane & 7) + ((lane >> 3) & 1) * 8;
    const uint32_t khoff = (uint32_t)(lane >> 4) * 2048;

    float acc[4][4][4] = {};
    const int NCH = NBLK * 16;

    #pragma unroll 1
    for (int c = 0; c < NCH; c++) {
        CP_WAIT0();          // chunk c (and A on first iter) resident
        __syncthreads();     // stage (c+1)&1 no longer being read (consumed in iter c-1)
        if (c + 1 < NCH) {
            const int c2 = c + 1;
            const size_t boff = (size_t)((c2 >> 4) * 128) * DIM + (c2 & 15) * 16;
            CP_ASYNC16(bDst + (c2 & 1) * B_STAGE, bRow + boff);
        }
        CP_COMMIT();

        const int kt = c & 15;
        const uint32_t sA = ABASE + kt * 4096 + khoff;
        const uint32_t sB = BBASE + (c & 1) * B_STAGE + khoff;

        unsigned bfr[4][2];
        #pragma unroll
        for (int j2 = 0; j2 < 2; j2++) {
            const uint32_t off = (uint32_t)(wn + j2 * 16 + rowsel) * 16;
            unsigned th[4];
            ldsm_x4(sB + off, th);
            bfr[2 * j2][0] = th[0]; bfr[2 * j2][1] = th[2];
            bfr[2 * j2 + 1][0] = th[1]; bfr[2 * j2 + 1][1] = th[3];
        }
        #pragma unroll
        for (int i = 0; i < 4; i++) {
            const uint32_t off = (uint32_t)(wm + i * 16 + rowsel) * 16;
            unsigned afr[4];
            ldsm_x4(sA + off, afr);
            #pragma unroll
            for (int j = 0; j < 4; j++)
                mma_fp16(acc[i][j], afr, bfr[j]);
        }

        if (kt == 15) {
            const int nb = (c >> 4) * 128;
            #pragma unroll
            for (int i = 0; i < 4; i++) {
                const int orow = mb + wm + i * 16 + g;
                const int r0 = SCATTER_OUT ? src_token(orow) : orow;
                const int r1 = SCATTER_OUT ? src_token(orow + 8) : (orow + 8);
                #pragma unroll
                for (int j = 0; j < 4; j++) {
                    int col = nb + wn + j * 8 + 2 * l4;
                    if (OUT_HALF) {
                        *(__half2*)&g_qkvh[(size_t)r0 * NOUT + col] =
                            __floats2half2_rn(acc[i][j][0], acc[i][j][1]);
                        *(__half2*)&g_qkvh[(size_t)r1 * NOUT + col] =
                            __floats2half2_rn(acc[i][j][2], acc[i][j][3]);
                    } else {
                        float bx = 0.f, by = 0.f;
                        if (SCATTER_OUT) { bx = bias[col]; by = bias[col + 1]; }
                        *(float2*)&OutExt[(size_t)r0 * NOUT + col] =
                            make_float2(acc[i][j][0] + bx, acc[i][j][1] + by);
                        *(float2*)&OutExt[(size_t)r1 * NOUT + col] =
                            make_float2(acc[i][j][2] + bx, acc[i][j][3] + by);
                    }
                    acc[i][j][0] = acc[i][j][1] = acc[i][j][2] = acc[i][j][3] = 0.f;
                }
            }
        }
    }
}

// ---------------- fp16 tensor-core attention (proven R14 version) -------------
__global__ __launch_bounds__(128) void attn_fp16() {
    __shared__ __half QS[64][40];
    __shared__ __half KS[64][40];
    __shared__ __half VT[32][72];
    __shared__ __half PS[4][16][72];

    const int wp = blockIdx.x, h = blockIdx.y;
    const int ap = wp / 144, bp = (wp / 12) % 12, cp = wp % 12;
    const int wqk = bp * 144 + cp * 12 + ap;
    const int tid = threadIdx.x;
    const int warp = tid >> 5, lane = tid & 31;
    const int g = lane >> 2, l4 = lane & 3;

    {
        const int r = tid >> 1, ch = (tid & 1) * 16;
        const __half* qg = g_qkvh + (size_t)(wqk * 64 + r) * QKVN + h * HD + ch;
        const __half* vg = g_qkvh + (size_t)(wp * 64 + r) * QKVN + 512 + h * HD + ch;
        *(uint4*)&QS[r][ch]     = *(const uint4*)qg;
        *(uint4*)&QS[r][ch + 8] = *(const uint4*)(qg + 8);
        *(uint4*)&KS[r][ch]     = *(const uint4*)(qg + 256);
        *(uint4*)&KS[r][ch + 8] = *(const uint4*)(qg + 256 + 8);
        #pragma unroll
        for (int e = 0; e < 16; e++) VT[ch + e][r] = vg[e];
    }
    __syncthreads();

    const int m0 = warp * 16;
    const int maskbits = ((bp == 11) << 5) | ((cp == 11) << 3) | ((ap == 11) << 1);
    const float scale = 0.1767766952966369f;

    const int rowsel = (lane & 7) + ((lane >> 3) & 1) * 8;
    const uint32_t coff = (uint32_t)(lane >> 4) * 16;
    const uint32_t QSb = (uint32_t)__cvta_generic_to_shared(QS);
    const uint32_t KSb = (uint32_t)__cvta_generic_to_shared(KS);
    const uint32_t VTb = (uint32_t)__cvta_generic_to_shared(VT);
    const uint32_t PSb = (uint32_t)__cvta_generic_to_shared(PS);

    float s[8][4] = {};
    #pragma unroll
    for (int kt = 0; kt < 2; kt++) {
        unsigned afr[4];
        ldsm_x4(QSb + (m0 + rowsel) * 80 + kt * 32 + coff, afr);
        #pragma unroll
        for (int j2 = 0; j2 < 4; j2++) {
            unsigned th[4];
            ldsm_x4(KSb + (j2 * 16 + rowsel) * 80 + kt * 32 + coff, th);
            unsigned b0[2] = {th[0], th[2]}, b1[2] = {th[1], th[3]};
            mma_fp16(s[2 * j2],     afr, b0);
            mma_fp16(s[2 * j2 + 1], afr, b1);
        }
    }

    const int i0 = m0 + g, i1 = m0 + g + 8;
    float mx0 = -1e30f, mx1 = -1e30f;
    #pragma unroll
    for (int nt = 0; nt < 8; nt++) {
        const int j0 = nt * 8 + 2 * l4;
        s[nt][0] = ((i0 ^ j0) & maskbits) ? -1e30f : s[nt][0] * scale;
        s[nt][1] = ((i0 ^ (j0 + 1)) & maskbits) ? -1e30f : s[nt][1] * scale;
        s[nt][2] = ((i1 ^ j0) & maskbits) ? -1e30f : s[nt][2] * scale;
        s[nt][3] = ((i1 ^ (j0 + 1)) & maskbits) ? -1e30f : s[nt][3] * scale;
        mx0 = fmaxf(mx0, fmaxf(s[nt][0], s[nt][1]));
        mx1 = fmaxf(mx1, fmaxf(s[nt][2], s[nt][3]));
    }
    mx0 = fmaxf(mx0, __shfl_xor_sync(0xFFFFFFFF, mx0, 1));
    mx0 = fmaxf(mx0, __shfl_xor_sync(0xFFFFFFFF, mx0, 2));
    mx1 = fmaxf(mx1, __shfl_xor_sync(0xFFFFFFFF, mx1, 1));
    mx1 = fmaxf(mx1, __shfl_xor_sync(0xFFFFFFFF, mx1, 2));
    float sm0 = 0.f, sm1 = 0.f;
    #pragma unroll
    for (int nt = 0; nt < 8; nt++) {
        s[nt][0] = __expf(s[nt][0] - mx0);
        s[nt][1] = __expf(s[nt][1] - mx0);
        s[nt][2] = __expf(s[nt][2] - mx1);
        s[nt][3] = __expf(s[nt][3] - mx1);
        sm0 += s[nt][0] + s[nt][1];
        sm1 += s[nt][2] + s[nt][3];
    }
    sm0 += __shfl_xor_sync(0xFFFFFFFF, sm0, 1);
    sm0 += __shfl_xor_sync(0xFFFFFFFF, sm0, 2);
    sm1 += __shfl_xor_sync(0xFFFFFFFF, sm1, 1);
    sm1 += __shfl_xor_sync(0xFFFFFFFF, sm1, 2);
    const float inv0 = 1.f / sm0, inv1 = 1.f / sm1;

    #pragma unroll
    for (int nt = 0; nt < 8; nt++) {
        const int j0 = nt * 8 + 2 * l4;
        *(__half2*)&PS[warp][g][j0]     = __floats2half2_rn(s[nt][0], s[nt][1]);
        *(__half2*)&PS[warp][g + 8][j0] = __floats2half2_rn(s[nt][2], s[nt][3]);
    }
    __syncwarp();

    float o[4][4] = {};
    const uint32_t PSw = PSb + warp * 16 * 144;
    #pragma unroll
    for (int kt = 0; kt < 4; kt++) {
        unsigned afr[4];
        ldsm_x4(PSw + rowsel * 144 + kt * 32 + coff, afr);
        #pragma unroll
        for (int d2 = 0; d2 < 2; d2++) {
            unsigned th[4];
            ldsm_x4(VTb + (d2 * 16 + rowsel) * 144 + kt * 32 + coff, th);
            unsigned b0[2] = {th[0], th[2]}, b1[2] = {th[1], th[3]};
            mma_fp16(o[2 * d2],     afr, b0);
            mma_fp16(o[2 * d2 + 1], afr, b1);
        }
    }

    const size_t off0 = (size_t)(wp * 64 + i0) * DIM + h * HD;
    const size_t off1 = (size_t)(wp * 64 + i1) * DIM + h * HD;
    #pragma unroll
    for (int dt = 0; dt < 4; dt++) {
        const int d0 = dt * 8 + 2 * l4;
        *(__half2*)&g_ah[off0 + d0] = __floats2half2_rn(o[dt][0] * inv0, o[dt][1] * inv0);
        *(__half2*)&g_ah[off1 + d0] = __floats2half2_rn(o[dt][2] * inv1, o[dt][3] * inv1);
    }
}

// ---------------- launch ----------------
extern "C" void kernel_launch(void* const* d_in, const int* in_sizes, int n_in,
                              void* d_out, int out_size) {
    const float* x     = (const float*)d_in[0];
    const float* w_qkv = (const float*)d_in[1];
    const float* w_out = (const float*)d_in[2];
    const float* b_out = (const float*)d_in[3];
    float* out = (float*)d_out;

    cudaFuncSetAttribute(gemm_fp16k<6, true, false, true>,
                         cudaFuncAttributeMaxDynamicSharedMemorySize, GEMM_SMEM);
    cudaFuncSetAttribute(gemm_fp16k<2, false, true, false>,
                         cudaFuncAttributeMaxDynamicSharedMemorySize, GEMM_SMEM);

    convert_x_kernel<<<NTOK * 64 / 256, 256>>>((const float4*)x);
    transpose_cvt<true> <<<dim3(QKVN / 32, DIM / 32), dim3(32, 8)>>>(w_qkv);
    transpose_cvt<false><<<dim3(DIM / 32,  DIM / 32), dim3(32, 8)>>>(w_out);
    gemm_fp16k<6, true, false, true><<<NTOK / 128, 256, GEMM_SMEM>>>(nullptr, nullptr);
    attn_fp16<<<dim3(NW, H), 128>>>();
    gemm_fp16k<2, false, true, false><<<NTOK / 128, 256, GEMM_SMEM>>>(b_out, out);
}

// round 16
// speedup vs baseline: 1.3796x; 1.3796x over previous
#include <cuda_runtime.h>
#include <cuda_fp16.h>
#include <cstdint>

// ---------------- problem constants ----------------
#define NS    48
#define DIM   256
#define H     8
#define HD    32
#define NW    1728
#define NTOK  110592
#define QKVN  768

// A-resident fp16 GEMM geometry (m-tile 128, 2 CTAs/SM, 3-stage B ring) — R14 config
#define A_BYTES   65536
#define B_STAGE   4096
#define B_STAGES  3
#define GEMM_SMEM (A_BYTES + B_STAGES * B_STAGE)   // 77824

// ---------------- scratch ----------------
__device__ __align__(16) __half g_qkvh[(size_t)NTOK * QKVN];
__device__ __align__(16) __half g_xh[(size_t)NTOK * DIM];
__device__ __align__(16) __half g_ah[(size_t)NTOK * DIM];
__device__ __align__(16) __half g_wqkv_h[(size_t)QKVN * DIM];
__device__ __align__(16) __half g_wout_h[(size_t)DIM * DIM];

__device__ __forceinline__ int src_token(int t) {
    int win = t >> 6, i = t & 63;
    int a = win / 144, b = (win / 12) % 12, c = win % 12;
    int ix = i >> 4, iy = (i >> 2) & 3, iz = i & 3;
    int X = a * 4 + ix + 2; if (X >= NS) X -= NS;
    int Y = b * 4 + iy + 2; if (Y >= NS) Y -= NS;
    int Z = c * 4 + iz + 2; if (Z >= NS) Z -= NS;
    return (X * NS + Y) * NS + Z;
}

// ---------------- MMA / ldmatrix / cp.async helpers ----------------
__device__ __forceinline__ void mma_fp16(float* d, const unsigned* a, const unsigned* b) {
    asm volatile(
        "mma.sync.aligned.m16n8k16.row.col.f32.f16.f16.f32 "
        "{%0,%1,%2,%3},{%4,%5,%6,%7},{%8,%9},{%0,%1,%2,%3};"
        : "+f"(d[0]), "+f"(d[1]), "+f"(d[2]), "+f"(d[3])
        : "r"(a[0]), "r"(a[1]), "r"(a[2]), "r"(a[3]), "r"(b[0]), "r"(b[1]));
}
__device__ __forceinline__ void ldsm_x4(uint32_t addr, unsigned r[4]) {
    asm volatile("ldmatrix.sync.aligned.m8n8.x4.shared.b16 {%0,%1,%2,%3}, [%4];"
                 : "=r"(r[0]), "=r"(r[1]), "=r"(r[2]), "=r"(r[3]) : "r"(addr));
}
#define CP_ASYNC16(dst, src) \
    asm volatile("cp.async.ca.shared.global [%0], [%1], 16;" :: "r"(dst), "l"(src) : "memory")
#define CP_COMMIT() asm volatile("cp.async.commit_group;" ::: "memory")
#define CP_WAIT1()  asm volatile("cp.async.wait_group 1;" ::: "memory")

// ---------------- prep kernels ----------------
__global__ __launch_bounds__(256) void convert_x_kernel(const float4* __restrict__ x) {
    size_t i = (size_t)blockIdx.x * blockDim.x + threadIdx.x;
    float4 v = x[i];
    ((__half2*)g_xh)[2 * i]     = __floats2half2_rn(v.x, v.y);
    ((__half2*)g_xh)[2 * i + 1] = __floats2half2_rn(v.z, v.w);
}

template<bool QKV>
__global__ void transpose_cvt(const float* __restrict__ W) {
    __shared__ float tile[32][33];
    const int N = QKV ? QKVN : DIM;
    __half* Wh = QKV ? g_wqkv_h : g_wout_h;
    int bx = blockIdx.x * 32, by = blockIdx.y * 32;
    #pragma unroll
    for (int i = 0; i < 32; i += 8)
        tile[threadIdx.y + i][threadIdx.x] = W[(size_t)(by + threadIdx.y + i) * N + bx + threadIdx.x];
    __syncthreads();
    #pragma unroll
    for (int i = 0; i < 32; i += 8)
        Wh[(size_t)(bx + threadIdx.y + i) * DIM + by + threadIdx.x] =
            __float2half_rn(tile[threadIdx.x][threadIdx.y + i]);
}

// ---------------- A-resident fp16 GEMM (R14 + hoisted LDSM) -------------------
template<int NBLK, bool GATHER_A, bool SCATTER_OUT, bool OUT_HALF>
__global__ __launch_bounds__(256, 2) void gemm_fp16k(
        const float* __restrict__ bias, float* __restrict__ OutExt) {
    extern __shared__ char smc[];
    const uint32_t ABASE = (uint32_t)__cvta_generic_to_shared(smc);
    const uint32_t BBASE = ABASE + A_BYTES;

    const int tid = threadIdx.x;
    const int warp = tid >> 5, lane = tid & 31;
    const int g = lane >> 2, l4 = lane & 3;
    const int wm = (warp >> 2) * 64, wn = (warp & 3) * 32;

    const __half* Ah = GATHER_A ? g_xh : g_ah;
    const __half* Bh = GATHER_A ? g_wqkv_h : g_wout_h;
    const int NOUT = NBLK * 128;

    const int mb = blockIdx.x * 128;
    const int lrow = tid & 127;
    const int half = tid >> 7;

    // ---- load A plane once ----
    {
        const int tok = GATHER_A ? src_token(mb + lrow) : (mb + lrow);
        const __half* a0 = Ah + (size_t)tok * DIM + half * 8;
        const uint32_t d0 = ABASE + half * 2048 + lrow * 16;
        #pragma unroll
        for (int kt = 0; kt < 16; kt++)
            CP_ASYNC16(d0 + kt * 4096, a0 + kt * 16);
        CP_COMMIT();
    }

    const __half* bRow = Bh + (size_t)lrow * DIM + half * 8;
    const uint32_t bDst = BBASE + half * 2048 + lrow * 16;

    #pragma unroll
    for (int p = 0; p < 2; p++) {
        CP_ASYNC16(bDst + p * B_STAGE, bRow + p * 16);
        CP_COMMIT();
    }

    const int rowsel = (lane & 7) + ((lane >> 3) & 1) * 8;
    const uint32_t khoff = (uint32_t)(lane >> 4) * 2048;

    float acc[4][4][4] = {};
    const int NCH = NBLK * 16;

    #pragma unroll 1
    for (int c = 0; c < NCH; c++) {
        CP_WAIT1();
        __syncthreads();
        if (c + 2 < NCH) {
            const int c2 = c + 2;
            const size_t boff = (size_t)((c2 >> 4) * 128) * DIM + (c2 & 15) * 16;
            CP_ASYNC16(bDst + (c2 % B_STAGES) * B_STAGE, bRow + boff);
        }
        CP_COMMIT();

        const int kt = c & 15;
        const uint32_t sA = ABASE + kt * 4096 + khoff;
        const uint32_t sB = BBASE + (c % B_STAGES) * B_STAGE + khoff;

        // ---- front-load ALL fragments of the chunk (single latency window) ----
        unsigned bfr[4][2], afr[4][4];
        #pragma unroll
        for (int j2 = 0; j2 < 2; j2++) {
            const uint32_t off = (uint32_t)(wn + j2 * 16 + rowsel) * 16;
            unsigned th[4];
            ldsm_x4(sB + off, th);
            bfr[2 * j2][0] = th[0]; bfr[2 * j2][1] = th[2];
            bfr[2 * j2 + 1][0] = th[1]; bfr[2 * j2 + 1][1] = th[3];
        }
        #pragma unroll
        for (int i = 0; i < 4; i++) {
            const uint32_t off = (uint32_t)(wm + i * 16 + rowsel) * 16;
            ldsm_x4(sA + off, afr[i]);
        }
        // ---- then all 16 MMAs back-to-back ----
        #pragma unroll
        for (int i = 0; i < 4; i++)
            #pragma unroll
            for (int j = 0; j < 4; j++)
                mma_fp16(acc[i][j], afr[i], bfr[j]);

        if (kt == 15) {
            const int nb = (c >> 4) * 128;
            #pragma unroll
            for (int i = 0; i < 4; i++) {
                const int orow = mb + wm + i * 16 + g;
                const int r0 = SCATTER_OUT ? src_token(orow) : orow;
                const int r1 = SCATTER_OUT ? src_token(orow + 8) : (orow + 8);
                #pragma unroll
                for (int j = 0; j < 4; j++) {
                    int col = nb + wn + j * 8 + 2 * l4;
                    if (OUT_HALF) {
                        *(__half2*)&g_qkvh[(size_t)r0 * NOUT + col] =
                            __floats2half2_rn(acc[i][j][0], acc[i][j][1]);
                        *(__half2*)&g_qkvh[(size_t)r1 * NOUT + col] =
                            __floats2half2_rn(acc[i][j][2], acc[i][j][3]);
                    } else {
                        float bx = 0.f, by = 0.f;
                        if (SCATTER_OUT) { bx = bias[col]; by = bias[col + 1]; }
                        *(float2*)&OutExt[(size_t)r0 * NOUT + col] =
                            make_float2(acc[i][j][0] + bx, acc[i][j][1] + by);
                        *(float2*)&OutExt[(size_t)r1 * NOUT + col] =
                            make_float2(acc[i][j][2] + bx, acc[i][j][3] + by);
                    }
                    acc[i][j][0] = acc[i][j][1] = acc[i][j][2] = acc[i][j][3] = 0.f;
                }
            }
        }
    }
}

// ---------------- fp16 tensor-core attention (proven R14 version) -------------
__global__ __launch_bounds__(128) void attn_fp16() {
    __shared__ __half QS[64][40];
    __shared__ __half KS[64][40];
    __shared__ __half VT[32][72];
    __shared__ __half PS[4][16][72];

    const int wp = blockIdx.x, h = blockIdx.y;
    const int ap = wp / 144, bp = (wp / 12) % 12, cp = wp % 12;
    const int wqk = bp * 144 + cp * 12 + ap;
    const int tid = threadIdx.x;
    const int warp = tid >> 5, lane = tid & 31;
    const int g = lane >> 2, l4 = lane & 3;

    {
        const int r = tid >> 1, ch = (tid & 1) * 16;
        const __half* qg = g_qkvh + (size_t)(wqk * 64 + r) * QKVN + h * HD + ch;
        const __half* vg = g_qkvh + (size_t)(wp * 64 + r) * QKVN + 512 + h * HD + ch;
        *(uint4*)&QS[r][ch]     = *(const uint4*)qg;
        *(uint4*)&QS[r][ch + 8] = *(const uint4*)(qg + 8);
        *(uint4*)&KS[r][ch]     = *(const uint4*)(qg + 256);
        *(uint4*)&KS[r][ch + 8] = *(const uint4*)(qg + 256 + 8);
        #pragma unroll
        for (int e = 0; e < 16; e++) VT[ch + e][r] = vg[e];
    }
    __syncthreads();

    const int m0 = warp * 16;
    const int maskbits = ((bp == 11) << 5) | ((cp == 11) << 3) | ((ap == 11) << 1);
    const float scale = 0.1767766952966369f;

    const int rowsel = (lane & 7) + ((lane >> 3) & 1) * 8;
    const uint32_t coff = (uint32_t)(lane >> 4) * 16;
    const uint32_t QSb = (uint32_t)__cvta_generic_to_shared(QS);
    const uint32_t KSb = (uint32_t)__cvta_generic_to_shared(KS);
    const uint32_t VTb = (uint32_t)__cvta_generic_to_shared(VT);
    const uint32_t PSb = (uint32_t)__cvta_generic_to_shared(PS);

    float s[8][4] = {};
    #pragma unroll
    for (int kt = 0; kt < 2; kt++) {
        unsigned afr[4];
        ldsm_x4(QSb + (m0 + rowsel) * 80 + kt * 32 + coff, afr);
        #pragma unroll
        for (int j2 = 0; j2 < 4; j2++) {
            unsigned th[4];
            ldsm_x4(KSb + (j2 * 16 + rowsel) * 80 + kt * 32 + coff, th);
            unsigned b0[2] = {th[0], th[2]}, b1[2] = {th[1], th[3]};
            mma_fp16(s[2 * j2],     afr, b0);
            mma_fp16(s[2 * j2 + 1], afr, b1);
        }
    }

    const int i0 = m0 + g, i1 = m0 + g + 8;
    float mx0 = -1e30f, mx1 = -1e30f;
    #pragma unroll
    for (int nt = 0; nt < 8; nt++) {
        const int j0 = nt * 8 + 2 * l4;
        s[nt][0] = ((i0 ^ j0) & maskbits) ? -1e30f : s[nt][0] * scale;
        s[nt][1] = ((i0 ^ (j0 + 1)) & maskbits) ? -1e30f : s[nt][1] * scale;
        s[nt][2] = ((i1 ^ j0) & maskbits) ? -1e30f : s[nt][2] * scale;
        s[nt][3] = ((i1 ^ (j0 + 1)) & maskbits) ? -1e30f : s[nt][3] * scale;
        mx0 = fmaxf(mx0, fmaxf(s[nt][0], s[nt][1]));
        mx1 = fmaxf(mx1, fmaxf(s[nt][2], s[nt][3]));
    }
    mx0 = fmaxf(mx0, __shfl_xor_sync(0xFFFFFFFF, mx0, 1));
    mx0 = fmaxf(mx0, __shfl_xor_sync(0xFFFFFFFF, mx0, 2));
    mx1 = fmaxf(mx1, __shfl_xor_sync(0xFFFFFFFF, mx1, 1));
    mx1 = fmaxf(mx1, __shfl_xor_sync(0xFFFFFFFF, mx1, 2));
    float sm0 = 0.f, sm1 = 0.f;
    #pragma unroll
    for (int nt = 0; nt < 8; nt++) {
        s[nt][0] = __expf(s[nt][0] - mx0);
        s[nt][1] = __expf(s[nt][1] - mx0);
        s[nt][2] = __expf(s[nt][2] - mx1);
        s[nt][3] = __expf(s[nt][3] - mx1);
        sm0 += s[nt][0] + s[nt][1];
        sm1 += s[nt][2] + s[nt][3];
    }
    sm0 += __shfl_xor_sync(0xFFFFFFFF, sm0, 1);
    sm0 += __shfl_xor_sync(0xFFFFFFFF, sm0, 2);
    sm1 += __shfl_xor_sync(0xFFFFFFFF, sm1, 1);
    sm1 += __shfl_xor_sync(0xFFFFFFFF, sm1, 2);
    const float inv0 = 1.f / sm0, inv1 = 1.f / sm1;

    #pragma unroll
    for (int nt = 0; nt < 8; nt++) {
        const int j0 = nt * 8 + 2 * l4;
        *(__half2*)&PS[warp][g][j0]     = __floats2half2_rn(s[nt][0], s[nt][1]);
        *(__half2*)&PS[warp][g + 8][j0] = __floats2half2_rn(s[nt][2], s[nt][3]);
    }
    __syncwarp();

    float o[4][4] = {};
    const uint32_t PSw = PSb + warp * 16 * 144;
    #pragma unroll
    for (int kt = 0; kt < 4; kt++) {
        unsigned afr[4];
        ldsm_x4(PSw + rowsel * 144 + kt * 32 + coff, afr);
        #pragma unroll
        for (int d2 = 0; d2 < 2; d2++) {
            unsigned th[4];
            ldsm_x4(VTb + (d2 * 16 + rowsel) * 144 + kt * 32 + coff, th);
            unsigned b0[2] = {th[0], th[2]}, b1[2] = {th[1], th[3]};
            mma_fp16(o[2 * d2],     afr, b0);
            mma_fp16(o[2 * d2 + 1], afr, b1);
        }
    }

    const size_t off0 = (size_t)(wp * 64 + i0) * DIM + h * HD;
    const size_t off1 = (size_t)(wp * 64 + i1) * DIM + h * HD;
    #pragma unroll
    for (int dt = 0; dt < 4; dt++) {
        const int d0 = dt * 8 + 2 * l4;
        *(__half2*)&g_ah[off0 + d0] = __floats2half2_rn(o[dt][0] * inv0, o[dt][1] * inv0);
        *(__half2*)&g_ah[off1 + d0] = __floats2half2_rn(o[dt][2] * inv1, o[dt][3] * inv1);
    }
}

// ---------------- launch ----------------
extern "C" void kernel_launch(void* const* d_in, const int* in_sizes, int n_in,
                              void* d_out, int out_size) {
    const float* x     = (const float*)d_in[0];
    const float* w_qkv = (const float*)d_in[1];
    const float* w_out = (const float*)d_in[2];
    const float* b_out = (const float*)d_in[3];
    float* out = (float*)d_out;

    cudaFuncSetAttribute(gemm_fp16k<6, true, false, true>,
                         cudaFuncAttributeMaxDynamicSharedMemorySize, GEMM_SMEM);
    cudaFuncSetAttribute(gemm_fp16k<2, false, true, false>,
                         cudaFuncAttributeMaxDynamicSharedMemorySize, GEMM_SMEM);

    convert_x_kernel<<<NTOK * 64 / 256, 256>>>((const float4*)x);
    transpose_cvt<true> <<<dim3(QKVN / 32, DIM / 32), dim3(32, 8)>>>(w_qkv);
    transpose_cvt<false><<<dim3(DIM / 32,  DIM / 32), dim3(32, 8)>>>(w_out);
    gemm_fp16k<6, true, false, true><<<NTOK / 128, 256, GEMM_SMEM>>>(nullptr, nullptr);
    attn_fp16<<<dim3(NW, H), 128>>>();
    gemm_fp16k<2, false, true, false><<<NTOK / 128, 256, GEMM_SMEM>>>(b_out, out);
}